// round 5
// baseline (speedup 1.0000x reference)
#include <cuda_runtime.h>
#include <cuda_fp16.h>
#include <cuda_fp8.h>

// Problem shapes (fixed by the dataset)
#define M_FULL  16384
#define N_DIM   4096
#define K_DIM   4096

// Scratch (allocation-free rule: __device__ globals)
__device__ float         g_Asum[(size_t)M_FULL * K_DIM / 2]; // generous: up to M_out=8192 rows
__device__ unsigned char g_B8[(size_t)K_DIM * N_DIM];        // 16 MB

// fp32 -> e4m3 -> fp32 round-trip (matches reference quantization)
__device__ __forceinline__ float fp8_round(float x) {
    __nv_fp8_storage_t s = __nv_cvt_float_to_fp8(x, __NV_SATFINITE, __NV_E4M3);
    __half_raw hr = __nv_cvt_fp8_to_halfraw(s, __NV_E4M3);
    return __half2float(__half(hr));
}

__device__ __forceinline__ float fp8_b2f(unsigned char b) {
    __half_raw hr = __nv_cvt_fp8_to_halfraw((__nv_fp8_storage_t)b, __NV_E4M3);
    return __half2float(__half(hr));
}

// Pass 1: Asum[i,k] = sum_w fp8round(A[w*M_out + i, k]); fp32 accumulate.
__global__ void reduce_quant_kernel(const float* __restrict__ A, int shard4, int world) {
    int idx = blockIdx.x * blockDim.x + threadIdx.x;
    if (idx >= shard4) return;
    const float4* A4 = (const float4*)A;
    float4 s = make_float4(0.f, 0.f, 0.f, 0.f);
    for (int w = 0; w < world; w++) {
        float4 v = A4[(size_t)w * shard4 + idx];
        s.x += fp8_round(v.x);
        s.y += fp8_round(v.y);
        s.z += fp8_round(v.z);
        s.w += fp8_round(v.w);
    }
    ((float4*)g_Asum)[idx] = s;
}

// Pass 2: quantize weight to fp8 bytes once.
__global__ void quantB_kernel(const float* __restrict__ W) {
    const int N4 = (K_DIM * N_DIM) / 4;
    int idx = blockIdx.x * blockDim.x + threadIdx.x;
    if (idx >= N4) return;
    float4 v = ((const float4*)W)[idx];
    uchar4 o;
    o.x = (unsigned char)__nv_cvt_float_to_fp8(v.x, __NV_SATFINITE, __NV_E4M3);
    o.y = (unsigned char)__nv_cvt_float_to_fp8(v.y, __NV_SATFINITE, __NV_E4M3);
    o.z = (unsigned char)__nv_cvt_float_to_fp8(v.z, __NV_SATFINITE, __NV_E4M3);
    o.w = (unsigned char)__nv_cvt_float_to_fp8(v.w, __NV_SATFINITE, __NV_E4M3);
    ((uchar4*)g_B8)[idx] = o;
}

// Pass 3: C = Asum @ dequant(B8) * scale_b -> fp16-rounded, stored as FLOAT32.
#define BM 128
#define BN 128
#define BK 16

__global__ __launch_bounds__(256, 2)
void gemm_kernel(const float* __restrict__ scale_b, float* __restrict__ out) {
    __shared__ float As[BK][BM];   // transposed A tile
    __shared__ float Bs[BK][BN];

    const int tid = threadIdx.x;
    const int bm = blockIdx.y * BM;
    const int bn = blockIdx.x * BN;
    const int tx = tid % 16;       // column group
    const int ty = tid / 16;       // row group

    float acc[8][8] = {};

    for (int k0 = 0; k0 < K_DIM; k0 += BK) {
#pragma unroll
        for (int i = 0; i < 2; i++) {
            int row = i * 64 + (tid >> 2);
            int col = (tid & 3) * 4;
            float4 v = *(const float4*)&g_Asum[(size_t)(bm + row) * K_DIM + k0 + col];
            As[col + 0][row] = v.x;
            As[col + 1][row] = v.y;
            As[col + 2][row] = v.z;
            As[col + 3][row] = v.w;
        }
        {
            int row = tid >> 4;            // 0..15
            int col = (tid & 15) * 8;      // 0..120
            uint2 raw = *(const uint2*)&g_B8[(size_t)(k0 + row) * N_DIM + bn + col];
            unsigned char b[8];
            *(uint2*)b = raw;
#pragma unroll
            for (int j = 0; j < 8; j++)
                Bs[row][col + j] = fp8_b2f(b[j]);
        }
        __syncthreads();

#pragma unroll
        for (int kk = 0; kk < BK; kk++) {
            float ra[8], rb[8];
#pragma unroll
            for (int i = 0; i < 8; i++) ra[i] = As[kk][ty * 8 + i];
#pragma unroll
            for (int j = 0; j < 8; j++) rb[j] = Bs[kk][tx * 8 + j];
#pragma unroll
            for (int i = 0; i < 8; i++)
#pragma unroll
                for (int j = 0; j < 8; j++)
                    acc[i][j] += ra[i] * rb[j];
        }
        __syncthreads();
    }

    // Epilogue: scale_b, fp16 quantize (match reference values), store as f32
#pragma unroll
    for (int i = 0; i < 8; i++) {
        int m = bm + ty * 8 + i;
#pragma unroll
        for (int j = 0; j < 8; j++) {
            int n = bn + tx * 8 + j;
            float v = acc[i][j] * scale_b[n];
            out[(size_t)m * N_DIM + n] = __half2float(__float2half(v));
        }
    }
}

extern "C" void kernel_launch(void* const* d_in, const int* in_sizes, int n_in,
                              void* d_out, int out_size) {
    // Bind inputs by SIZE (robust to ordering):
    const float* input   = nullptr;
    const float* weight  = nullptr;
    const float* scale_b = nullptr;
    long long input_elems = 0;
    for (int i = 0; i < n_in; i++) {
        long long sz = in_sizes[i];
        if (sz == (long long)K_DIM * N_DIM && !weight)      weight = (const float*)d_in[i];
        else if (sz == N_DIM && !scale_b)                   scale_b = (const float*)d_in[i];
        else if (sz > (long long)K_DIM * N_DIM)             { input = (const float*)d_in[i]; input_elems = sz; }
    }
    float* out = (float*)d_out;   // harness output buffer is FLOAT32

    long long M_full   = input_elems / K_DIM;            // 16384
    long long out_rows = (long long)out_size / N_DIM;    // 2048
    int world = (int)(M_full / (out_rows > 0 ? out_rows : M_full));
    if (world < 1) world = 1;
    int M_out = (int)(M_full / world);                   // 2048

    {
        int shard4 = (M_out * K_DIM) / 4;
        reduce_quant_kernel<<<(shard4 + 255) / 256, 256>>>(input, shard4, world);
    }
    {
        int n4 = (K_DIM * N_DIM) / 4;
        quantB_kernel<<<(n4 + 255) / 256, 256>>>(weight);
    }
    {
        dim3 grid(N_DIM / BN, M_out / BM);
        gemm_kernel<<<grid, 256>>>(scale_b, out);
    }
}

// round 6
// speedup vs baseline: 3.8986x; 3.8986x over previous
#include <cuda_runtime.h>
#include <cuda_fp16.h>
#include <cuda_fp8.h>
#include <mma.h>

using namespace nvcuda;

// Problem shapes (fixed by the dataset)
#define M_FULL  16384
#define N_DIM   4096
#define K_DIM   4096

// Scratch (allocation-free rule: __device__ globals)
__device__ __half g_A16[(size_t)(M_FULL / 2) * K_DIM];  // fp16 Asum (cap M_out<=8192)
__device__ __half g_B16[(size_t)K_DIM * N_DIM];          // fp16 dequantized fp8 weight

// fp32 -> e4m3 -> fp32 round-trip (matches reference quantization)
__device__ __forceinline__ float fp8_round(float x) {
    __nv_fp8_storage_t s = __nv_cvt_float_to_fp8(x, __NV_SATFINITE, __NV_E4M3);
    __half_raw hr = __nv_cvt_fp8_to_halfraw(s, __NV_E4M3);
    return __half2float(__half(hr));
}

__device__ __forceinline__ __half fp8_to_half(float x) {
    __nv_fp8_storage_t s = __nv_cvt_float_to_fp8(x, __NV_SATFINITE, __NV_E4M3);
    __half_raw hr = __nv_cvt_fp8_to_halfraw(s, __NV_E4M3);  // e4m3 exact in fp16
    return __half(hr);
}

// Pass 1: Asum[i,k] = sum_w fp8round(A[w*M_out+i, k]) in fp32, stored fp16.
__global__ void reduce_quant_kernel(const float* __restrict__ A, int shard4, int world) {
    int idx = blockIdx.x * blockDim.x + threadIdx.x;
    if (idx >= shard4) return;
    const float4* A4 = (const float4*)A;
    float4 s = make_float4(0.f, 0.f, 0.f, 0.f);
    for (int w = 0; w < world; w++) {
        float4 v = A4[(size_t)w * shard4 + idx];
        s.x += fp8_round(v.x);
        s.y += fp8_round(v.y);
        s.z += fp8_round(v.z);
        s.w += fp8_round(v.w);
    }
    __half2 lo = __floats2half2_rn(s.x, s.y);
    __half2 hi = __floats2half2_rn(s.z, s.w);
    ((__half2*)g_A16)[idx * 2 + 0] = lo;
    ((__half2*)g_A16)[idx * 2 + 1] = hi;
}

// Pass 2: weight -> e4m3 -> fp16 (exact), stored fp16.
__global__ void quantB_kernel(const float* __restrict__ W) {
    const int N4 = (K_DIM * N_DIM) / 4;
    int idx = blockIdx.x * blockDim.x + threadIdx.x;
    if (idx >= N4) return;
    float4 v = ((const float4*)W)[idx];
    __half2 lo = __halves2half2(fp8_to_half(v.x), fp8_to_half(v.y));
    __half2 hi = __halves2half2(fp8_to_half(v.z), fp8_to_half(v.w));
    ((__half2*)g_B16)[idx * 2 + 0] = lo;
    ((__half2*)g_B16)[idx * 2 + 1] = hi;
}

// Pass 3: tensor-core GEMM, raw fp32 accumulators to out.
#define BM 128
#define BN 128
#define BK 32
#define APAD 8
#define BPAD 8

__global__ __launch_bounds__(256, 1)
void gemm_wmma_kernel(float* __restrict__ out, int M_out) {
    __shared__ __half As[2][BM][BK + APAD];
    __shared__ __half Bs[2][BK][BN + BPAD];

    const int tid = threadIdx.x;
    const int bm = blockIdx.y * BM;
    const int bn = blockIdx.x * BN;
    const int warp = tid >> 5;
    const int warp_m = warp & 1;   // 0..1  -> 64-row group
    const int warp_n = warp >> 1;  // 0..3  -> 32-col group

    wmma::fragment<wmma::accumulator, 16, 16, 16, float> c[4][2];
#pragma unroll
    for (int i = 0; i < 4; i++)
#pragma unroll
        for (int j = 0; j < 2; j++) wmma::fill_fragment(c[i][j], 0.0f);

    // Tile-load id mapping: 2 uint4 per thread per matrix
    const int id0 = tid * 2, id1 = tid * 2 + 1;
    // A: 128 rows x 32 cols = 4 uint4/row
    const int a_r0 = id0 >> 2, a_c0 = (id0 & 3) * 8;
    const int a_r1 = id1 >> 2, a_c1 = (id1 & 3) * 8;
    // B: 32 rows x 128 cols = 16 uint4/row
    const int b_r0 = id0 >> 4, b_c0 = (id0 & 15) * 8;
    const int b_r1 = id1 >> 4, b_c1 = (id1 & 15) * 8;

    const __half* Ag = g_A16 + (size_t)bm * K_DIM;
    const __half* Bg = g_B16 + bn;

    // Preload tile 0
    {
        *(uint4*)&As[0][a_r0][a_c0] = *(const uint4*)&Ag[(size_t)a_r0 * K_DIM + a_c0];
        *(uint4*)&As[0][a_r1][a_c1] = *(const uint4*)&Ag[(size_t)a_r1 * K_DIM + a_c1];
        *(uint4*)&Bs[0][b_r0][b_c0] = *(const uint4*)&Bg[(size_t)b_r0 * N_DIM + b_c0];
        *(uint4*)&Bs[0][b_r1][b_c1] = *(const uint4*)&Bg[(size_t)b_r1 * N_DIM + b_c1];
    }
    __syncthreads();

    const int niter = K_DIM / BK;
    int buf = 0;
    for (int it = 0; it < niter; it++) {
        uint4 ra0, ra1, rb0, rb1;
        const bool has_next = (it + 1 < niter);
        if (has_next) {
            int k0 = (it + 1) * BK;
            ra0 = *(const uint4*)&Ag[(size_t)a_r0 * K_DIM + k0 + a_c0];
            ra1 = *(const uint4*)&Ag[(size_t)a_r1 * K_DIM + k0 + a_c1];
            rb0 = *(const uint4*)&Bg[(size_t)(k0 + b_r0) * N_DIM + b_c0];
            rb1 = *(const uint4*)&Bg[(size_t)(k0 + b_r1) * N_DIM + b_c1];
        }

        // Compute on current buffer (hides the LDGs above)
#pragma unroll
        for (int kk = 0; kk < BK; kk += 16) {
            wmma::fragment<wmma::matrix_a, 16, 16, 16, __half, wmma::row_major> a[4];
            wmma::fragment<wmma::matrix_b, 16, 16, 16, __half, wmma::row_major> b[2];
#pragma unroll
            for (int i = 0; i < 4; i++)
                wmma::load_matrix_sync(a[i], &As[buf][warp_m * 64 + i * 16][kk], BK + APAD);
#pragma unroll
            for (int j = 0; j < 2; j++)
                wmma::load_matrix_sync(b[j], &Bs[buf][kk][warp_n * 32 + j * 16], BN + BPAD);
#pragma unroll
            for (int i = 0; i < 4; i++)
#pragma unroll
                for (int j = 0; j < 2; j++)
                    wmma::mma_sync(c[i][j], a[i], b[j], c[i][j]);
        }

        if (has_next) {
            *(uint4*)&As[buf ^ 1][a_r0][a_c0] = ra0;
            *(uint4*)&As[buf ^ 1][a_r1][a_c1] = ra1;
            *(uint4*)&Bs[buf ^ 1][b_r0][b_c0] = rb0;
            *(uint4*)&Bs[buf ^ 1][b_r1][b_c1] = rb1;
        }
        __syncthreads();
        buf ^= 1;
    }

    // Raw accumulators to gmem (scale+round applied by epilogue kernel)
#pragma unroll
    for (int i = 0; i < 4; i++)
#pragma unroll
        for (int j = 0; j < 2; j++) {
            float* dst = out + (size_t)(bm + warp_m * 64 + i * 16) * N_DIM
                             + bn + warp_n * 32 + j * 16;
            wmma::store_matrix_sync(dst, c[i][j], N_DIM, wmma::mem_row_major);
        }
}

// Pass 4: in-place scale_b + fp16 quantize (values as fp32).
__global__ void epilogue_kernel(float* __restrict__ out,
                                const float* __restrict__ scale_b, int total4) {
    int idx = blockIdx.x * blockDim.x + threadIdx.x;
    if (idx >= total4) return;
    int col = (idx * 4) & (N_DIM - 1);
    float4 v = ((const float4*)out)[idx];
    float4 s = *(const float4*)&scale_b[col];
    v.x = __half2float(__float2half(v.x * s.x));
    v.y = __half2float(__float2half(v.y * s.y));
    v.z = __half2float(__float2half(v.z * s.z));
    v.w = __half2float(__float2half(v.w * s.w));
    ((float4*)out)[idx] = v;
}

extern "C" void kernel_launch(void* const* d_in, const int* in_sizes, int n_in,
                              void* d_out, int out_size) {
    const float* input   = nullptr;
    const float* weight  = nullptr;
    const float* scale_b = nullptr;
    long long input_elems = 0;
    for (int i = 0; i < n_in; i++) {
        long long sz = in_sizes[i];
        if (sz == (long long)K_DIM * N_DIM && !weight)      weight = (const float*)d_in[i];
        else if (sz == N_DIM && !scale_b)                   scale_b = (const float*)d_in[i];
        else if (sz > (long long)K_DIM * N_DIM)             { input = (const float*)d_in[i]; input_elems = sz; }
    }
    float* out = (float*)d_out;   // harness output buffer is FLOAT32

    long long M_full   = input_elems / K_DIM;            // 16384
    long long out_rows = (long long)out_size / N_DIM;    // 2048
    int world = (int)(M_full / (out_rows > 0 ? out_rows : M_full));
    if (world < 1) world = 1;
    int M_out = (int)(M_full / world);                   // 2048

    {
        int shard4 = (M_out * K_DIM) / 4;
        reduce_quant_kernel<<<(shard4 + 255) / 256, 256>>>(input, shard4, world);
    }
    {
        int n4 = (K_DIM * N_DIM) / 4;
        quantB_kernel<<<(n4 + 255) / 256, 256>>>(weight);
    }
    {
        dim3 grid(N_DIM / BN, M_out / BM);
        gemm_wmma_kernel<<<grid, 256>>>(out, M_out);
    }
    {
        int total4 = (M_out * N_DIM) / 4;
        epilogue_kernel<<<(total4 + 255) / 256, 256>>>(out, scale_b, total4);
    }
}

// round 8
// speedup vs baseline: 6.3251x; 1.6224x over previous
#include <cuda_runtime.h>
#include <cuda_fp16.h>
#include <cuda_fp8.h>
#include <cstdint>

// Problem shapes (fixed by the dataset)
#define M_FULL  16384
#define N_DIM   4096
#define K_DIM   4096

// Scratch (allocation-free rule: __device__ globals)
__device__ __half g_A16[(size_t)(M_FULL / 2) * K_DIM];  // fp16 Asum [M][K]
__device__ __half g_B16[(size_t)K_DIM * N_DIM];          // fp16 B^T [N][K]

// ---------------------------------------------------------------------------
// fp8 helpers
// ---------------------------------------------------------------------------
__device__ __forceinline__ float fp8_round(float x) {
    __nv_fp8_storage_t s = __nv_cvt_float_to_fp8(x, __NV_SATFINITE, __NV_E4M3);
    __half_raw hr = __nv_cvt_fp8_to_halfraw(s, __NV_E4M3);
    return __half2float(__half(hr));
}
__device__ __forceinline__ __half fp8_to_half(float x) {
    __nv_fp8_storage_t s = __nv_cvt_float_to_fp8(x, __NV_SATFINITE, __NV_E4M3);
    __half_raw hr = __nv_cvt_fp8_to_halfraw(s, __NV_E4M3);  // e4m3 exact in fp16
    return __half(hr);
}

// ---------------------------------------------------------------------------
// Pass 1: Asum[i,k] = sum_w fp8round(A[w*M_out+i, k]) in fp32, stored fp16.
// ---------------------------------------------------------------------------
__global__ void reduce_quant_kernel(const float* __restrict__ A, int shard4, int world) {
    int idx = blockIdx.x * blockDim.x + threadIdx.x;
    if (idx >= shard4) return;
    const float4* A4 = (const float4*)A;
    float4 s = make_float4(0.f, 0.f, 0.f, 0.f);
    for (int w = 0; w < world; w++) {
        float4 v = A4[(size_t)w * shard4 + idx];
        s.x += fp8_round(v.x);
        s.y += fp8_round(v.y);
        s.z += fp8_round(v.z);
        s.w += fp8_round(v.w);
    }
    ((__half2*)g_A16)[idx * 2 + 0] = __floats2half2_rn(s.x, s.y);
    ((__half2*)g_A16)[idx * 2 + 1] = __floats2half2_rn(s.z, s.w);
}

// ---------------------------------------------------------------------------
// Pass 2: W [K][N] f32 -> g_B16 = B^T [N][K] fp16 (K contiguous)
// ---------------------------------------------------------------------------
__global__ void quantBT_kernel(const float* __restrict__ W) {
    __shared__ float t[32][33];
    int n0 = blockIdx.x * 32, k0 = blockIdx.y * 32;
    int tx = threadIdx.x, ty = threadIdx.y;   // (32, 8)
#pragma unroll
    for (int i = 0; i < 4; i++)
        t[ty + 8 * i][tx] = W[(size_t)(k0 + ty + 8 * i) * N_DIM + n0 + tx];
    __syncthreads();
#pragma unroll
    for (int i = 0; i < 4; i++)
        g_B16[(size_t)(n0 + ty + 8 * i) * K_DIM + k0 + tx] = fp8_to_half(t[tx][ty + 8 * i]);
}

// ---------------------------------------------------------------------------
// PTX helpers (sm_80-era instructions; valid on compute_103)
// ---------------------------------------------------------------------------
__device__ __forceinline__ uint32_t smem_u32(const void* p) {
    uint32_t a;
    asm("{ .reg .u64 t; cvta.to.shared.u64 t, %1; cvt.u32.u64 %0, t; }" : "=r"(a) : "l"(p));
    return a;
}
__device__ __forceinline__ void ldsm_x4(uint32_t& r0, uint32_t& r1, uint32_t& r2, uint32_t& r3,
                                        uint32_t addr) {
    asm volatile("ldmatrix.sync.aligned.m8n8.x4.shared.b16 {%0,%1,%2,%3}, [%4];"
                 : "=r"(r0), "=r"(r1), "=r"(r2), "=r"(r3) : "r"(addr));
}
__device__ __forceinline__ void mma_16816(float* c, const uint32_t* a, uint32_t b0, uint32_t b1) {
    asm volatile("mma.sync.aligned.m16n8k16.row.col.f32.f16.f16.f32 "
                 "{%0,%1,%2,%3}, {%4,%5,%6,%7}, {%8,%9}, {%0,%1,%2,%3};"
                 : "+f"(c[0]), "+f"(c[1]), "+f"(c[2]), "+f"(c[3])
                 : "r"(a[0]), "r"(a[1]), "r"(a[2]), "r"(a[3]), "r"(b0), "r"(b1));
}
__device__ __forceinline__ void cp16(uint32_t smem, const void* g) {
    asm volatile("cp.async.cg.shared.global [%0], [%1], 16;" :: "r"(smem), "l"(g) : "memory");
}
#define CP_COMMIT() asm volatile("cp.async.commit_group;" ::: "memory")
#define CP_WAIT(n)  asm volatile("cp.async.wait_group %0;" :: "n"(n) : "memory")

// ---------------------------------------------------------------------------
// Pass 3: mma.sync GEMM 128x128x(K), BK=64 halves, 3-stage cp.async pipeline,
//         fused scale_b + fp16-round epilogue.  D = Asum @ W  (B as B^T [N][K])
// ---------------------------------------------------------------------------
#define BM 128
#define BN 128
#define BKH 64                       // halves per stage chunk (128 B rows)
#define STAGES 3
#define ROWB 128                     // bytes per smem row
#define A_STAGE (BM * ROWB)          // 16 KB
#define B_STAGE (BN * ROWB)          // 16 KB
#define STAGE_BYTES (A_STAGE + B_STAGE)
#define GEMM_SMEM (STAGES * STAGE_BYTES)

__device__ __forceinline__ uint32_t sw_off(int row, int chunk) {
    return (uint32_t)(row * ROWB + ((chunk ^ (row & 7)) << 4));
}

__global__ __launch_bounds__(256, 1)
void gemm_mma_kernel(const float* __restrict__ scale_b, float* __restrict__ out) {
    extern __shared__ char sm[];
    const uint32_t sbase = smem_u32(sm);

    const int tid  = threadIdx.x;
    const int lane = tid & 31;
    const int warp = tid >> 5;
    const int wm   = warp & 1;        // 0..1 -> 64-row group
    const int wn   = warp >> 1;       // 0..3 -> 32-col group
    const int bm = blockIdx.y * BM;
    const int bn = blockIdx.x * BN;

    const __half* Ag = g_A16 + (size_t)bm * K_DIM;
    const __half* Bg = g_B16 + (size_t)bn * K_DIM;

    // cp.async mapping: each thread owns chunk (tid&7), rows tid>>3 + {0,32,64,96}
    const int crow = tid >> 3;
    const int cchk = tid & 7;

    float acc[4][4][4] = {};          // [mi][n8][reg]

    const int KITER = K_DIM / BKH;    // 64

    // Prologue: stages 0..STAGES-2
#pragma unroll
    for (int s = 0; s < STAGES - 1; s++) {
        const __half* ga = Ag + (size_t)s * BKH + cchk * 8;
        const __half* gb = Bg + (size_t)s * BKH + cchk * 8;
        uint32_t as = sbase + s * STAGE_BYTES;
        uint32_t bs = as + A_STAGE;
#pragma unroll
        for (int i = 0; i < 4; i++) {
            int r = crow + i * 32;
            cp16(as + sw_off(r, cchk), ga + (size_t)r * K_DIM);
            cp16(bs + sw_off(r, cchk), gb + (size_t)r * K_DIM);
        }
        CP_COMMIT();
    }

    for (int it = 0; it < KITER; it++) {
        CP_WAIT(STAGES - 2);
        __syncthreads();

        // Issue next stage loads (overlap with compute below)
        int nk = it + STAGES - 1;
        if (nk < KITER) {
            int s = nk % STAGES;
            const __half* ga = Ag + (size_t)nk * BKH + cchk * 8;
            const __half* gb = Bg + (size_t)nk * BKH + cchk * 8;
            uint32_t as = sbase + s * STAGE_BYTES;
            uint32_t bs = as + A_STAGE;
#pragma unroll
            for (int i = 0; i < 4; i++) {
                int r = crow + i * 32;
                cp16(as + sw_off(r, cchk), ga + (size_t)r * K_DIM);
                cp16(bs + sw_off(r, cchk), gb + (size_t)r * K_DIM);
            }
            CP_COMMIT();
        } else {
            CP_COMMIT();   // keep group count in step with CP_WAIT bound
        }

        // Compute on stage it%STAGES
        const uint32_t As = sbase + (it % STAGES) * STAGE_BYTES;
        const uint32_t Bs = As + A_STAGE;
#pragma unroll
        for (int ks = 0; ks < 4; ks++) {
            const int ch = ks * 2 + (lane >> 4);
            uint32_t a[4][4];
#pragma unroll
            for (int mi = 0; mi < 4; mi++) {
                int r = wm * 64 + mi * 16 + (lane & 15);
                ldsm_x4(a[mi][0], a[mi][1], a[mi][2], a[mi][3], As + sw_off(r, ch));
            }
            uint32_t b[2][4];
#pragma unroll
            for (int nj = 0; nj < 2; nj++) {
                int r = wn * 32 + nj * 16 + (lane & 15);
                ldsm_x4(b[nj][0], b[nj][1], b[nj][2], b[nj][3], Bs + sw_off(r, ch));
            }
#pragma unroll
            for (int mi = 0; mi < 4; mi++)
#pragma unroll
                for (int n8 = 0; n8 < 4; n8++) {
                    int nj = n8 >> 1, hi = n8 & 1;
                    mma_16816(acc[mi][n8], a[mi], b[nj][hi], b[nj][hi + 2]);
                }
        }
        __syncthreads();
    }

    // Fused epilogue: scale_b + fp16 quantize, store fp32
#pragma unroll
    for (int mi = 0; mi < 4; mi++) {
#pragma unroll
        for (int n8 = 0; n8 < 4; n8++) {
            const float* c = acc[mi][n8];
            int row = bm + wm * 64 + mi * 16 + (lane >> 2);
            int col = bn + wn * 32 + n8 * 8 + (lane & 3) * 2;
            float2 s0 = *(const float2*)&scale_b[col];
            float2 v0;
            v0.x = __half2float(__float2half(c[0] * s0.x));
            v0.y = __half2float(__float2half(c[1] * s0.y));
            *(float2*)&out[(size_t)row * N_DIM + col] = v0;
            float2 v1;
            v1.x = __half2float(__float2half(c[2] * s0.x));
            v1.y = __half2float(__float2half(c[3] * s0.y));
            *(float2*)&out[(size_t)(row + 8) * N_DIM + col] = v1;
        }
    }
}

// ---------------------------------------------------------------------------
// Host
// ---------------------------------------------------------------------------
extern "C" void kernel_launch(void* const* d_in, const int* in_sizes, int n_in,
                              void* d_out, int out_size) {
    const float* input = nullptr; const float* weight = nullptr; const float* scale_b = nullptr;
    long long input_elems = 0;
    for (int i = 0; i < n_in; i++) {
        long long sz = in_sizes[i];
        if (sz == (long long)K_DIM * N_DIM && !weight)      weight = (const float*)d_in[i];
        else if (sz == N_DIM && !scale_b)                   scale_b = (const float*)d_in[i];
        else if (sz > (long long)K_DIM * N_DIM)             { input = (const float*)d_in[i]; input_elems = sz; }
    }
    float* out = (float*)d_out;   // harness output buffer is FLOAT32

    long long M_full   = input_elems / K_DIM;
    long long out_rows = (long long)out_size / N_DIM;
    int world = (int)(M_full / (out_rows > 0 ? out_rows : M_full));
    if (world < 1) world = 1;
    int M_out = (int)(M_full / world);

    {
        int shard4 = (M_out * K_DIM) / 4;
        reduce_quant_kernel<<<(shard4 + 255) / 256, 256>>>(input, shard4, world);
    }
    {
        dim3 tg(32, 8);
        quantBT_kernel<<<dim3(N_DIM / 32, K_DIM / 32), tg>>>(weight);
    }
    {
        cudaFuncSetAttribute(gemm_mma_kernel, cudaFuncAttributeMaxDynamicSharedMemorySize,
                             GEMM_SMEM);
        dim3 grid(N_DIM / BN, M_out / BM);
        gemm_mma_kernel<<<grid, 256, GEMM_SMEM>>>(scale_b, out);
    }
}

// round 9
// speedup vs baseline: 6.3960x; 1.0112x over previous
#include <cuda_runtime.h>
#include <cuda_fp16.h>
#include <cuda_fp8.h>
#include <cstdint>

// Problem shapes (fixed by the dataset)
#define M_FULL  16384
#define N_DIM   4096
#define K_DIM   4096

// Scratch (allocation-free rule: __device__ globals)
__device__ __half g_A16[(size_t)(M_FULL / 2) * K_DIM];  // fp16 Asum [M][K]
__device__ __half g_B16[(size_t)K_DIM * N_DIM];          // fp16 B^T [N][K]

// ---------------------------------------------------------------------------
// fp8 helpers
// ---------------------------------------------------------------------------
__device__ __forceinline__ float fp8_round(float x) {
    __nv_fp8_storage_t s = __nv_cvt_float_to_fp8(x, __NV_SATFINITE, __NV_E4M3);
    __half_raw hr = __nv_cvt_fp8_to_halfraw(s, __NV_E4M3);
    return __half2float(__half(hr));
}
__device__ __forceinline__ __half fp8_to_half(float x) {
    __nv_fp8_storage_t s = __nv_cvt_float_to_fp8(x, __NV_SATFINITE, __NV_E4M3);
    __half_raw hr = __nv_cvt_fp8_to_halfraw(s, __NV_E4M3);  // e4m3 exact in fp16
    return __half(hr);
}

// ---------------------------------------------------------------------------
// Fused prep kernel (both halves DRAM-bound; one launch keeps HBM saturated):
//   part 1 (blocks [0, rblocks)): Asum = sum_w fp8round(A_w), fp32 acc -> fp16
//   part 2 (rest):               W [K][N] f32 -> g_B16 = B^T [N][K] fp16
// ---------------------------------------------------------------------------
__global__ __launch_bounds__(256)
void prep_kernel(const float* __restrict__ A, const float* __restrict__ W,
                 int shard4, int world, int rblocks) {
    if ((int)blockIdx.x < rblocks) {
        int idx = blockIdx.x * 256 + threadIdx.x;
        if (idx >= shard4) return;
        const float4* A4 = (const float4*)A;
        float4 s = make_float4(0.f, 0.f, 0.f, 0.f);
        for (int w = 0; w < world; w++) {
            float4 v = A4[(size_t)w * shard4 + idx];
            s.x += fp8_round(v.x);
            s.y += fp8_round(v.y);
            s.z += fp8_round(v.z);
            s.w += fp8_round(v.w);
        }
        ((__half2*)g_A16)[idx * 2 + 0] = __floats2half2_rn(s.x, s.y);
        ((__half2*)g_A16)[idx * 2 + 1] = __floats2half2_rn(s.z, s.w);
    } else {
        __shared__ float t[32][33];
        int q = blockIdx.x - rblocks;              // 0 .. 128*128-1
        int n0 = (q & 127) * 32;
        int k0 = (q >> 7) * 32;
        int tx = threadIdx.x & 31, ty = threadIdx.x >> 5;   // (32, 8)
#pragma unroll
        for (int i = 0; i < 4; i++)
            t[ty + 8 * i][tx] = W[(size_t)(k0 + ty + 8 * i) * N_DIM + n0 + tx];
        __syncthreads();
#pragma unroll
        for (int i = 0; i < 4; i++)
            g_B16[(size_t)(n0 + ty + 8 * i) * K_DIM + k0 + tx] = fp8_to_half(t[tx][ty + 8 * i]);
    }
}

// ---------------------------------------------------------------------------
// PTX helpers (sm_80-era instructions; valid on compute_103)
// ---------------------------------------------------------------------------
__device__ __forceinline__ uint32_t smem_u32(const void* p) {
    uint32_t a;
    asm("{ .reg .u64 t; cvta.to.shared.u64 t, %1; cvt.u32.u64 %0, t; }" : "=r"(a) : "l"(p));
    return a;
}
__device__ __forceinline__ void ldsm_x4(uint32_t& r0, uint32_t& r1, uint32_t& r2, uint32_t& r3,
                                        uint32_t addr) {
    asm volatile("ldmatrix.sync.aligned.m8n8.x4.shared.b16 {%0,%1,%2,%3}, [%4];"
                 : "=r"(r0), "=r"(r1), "=r"(r2), "=r"(r3) : "r"(addr));
}
__device__ __forceinline__ void mma_16816(float* c, const uint32_t* a, uint32_t b0, uint32_t b1) {
    asm volatile("mma.sync.aligned.m16n8k16.row.col.f32.f16.f16.f32 "
                 "{%0,%1,%2,%3}, {%4,%5,%6,%7}, {%8,%9}, {%0,%1,%2,%3};"
                 : "+f"(c[0]), "+f"(c[1]), "+f"(c[2]), "+f"(c[3])
                 : "r"(a[0]), "r"(a[1]), "r"(a[2]), "r"(a[3]), "r"(b0), "r"(b1));
}
__device__ __forceinline__ void cp16(uint32_t smem, const void* g) {
    asm volatile("cp.async.cg.shared.global [%0], [%1], 16;" :: "r"(smem), "l"(g) : "memory");
}
#define CP_COMMIT() asm volatile("cp.async.commit_group;" ::: "memory")
#define CP_WAIT(n)  asm volatile("cp.async.wait_group %0;" :: "n"(n) : "memory")

// ---------------------------------------------------------------------------
// GEMM: 128x256 CTA tile, warp tile 64x64, BK=64 halves, 4-stage cp.async,
//       fused scale_b + fp16-round epilogue.  D = Asum @ W  (B as B^T [N][K])
// ---------------------------------------------------------------------------
#define BM 128
#define BN 256
#define BKH 64                        // halves per stage chunk (128 B rows)
#define STAGES 4
#define ROWB 128                      // bytes per smem row
#define A_STAGE (BM * ROWB)           // 16 KB
#define B_STAGE (BN * ROWB)           // 32 KB
#define STAGE_BYTES (A_STAGE + B_STAGE)
#define GEMM_SMEM (STAGES * STAGE_BYTES)   // 192 KB

__device__ __forceinline__ uint32_t sw_off(int row, int chunk) {
    return (uint32_t)(row * ROWB + ((chunk ^ (row & 7)) << 4));
}

__global__ __launch_bounds__(256, 1)
void gemm_mma_kernel(const float* __restrict__ scale_b, float* __restrict__ out) {
    extern __shared__ char sm[];
    const uint32_t sbase = smem_u32(sm);

    const int tid  = threadIdx.x;
    const int lane = tid & 31;
    const int warp = tid >> 5;
    const int wm   = warp & 1;        // 0..1 -> 64-row group
    const int wn   = warp >> 1;       // 0..3 -> 64-col group
    const int bm = blockIdx.y * BM;
    const int bn = blockIdx.x * BN;

    const __half* Ag = g_A16 + (size_t)bm * K_DIM;
    const __half* Bg = g_B16 + (size_t)bn * K_DIM;

    // cp.async mapping: thread owns chunk (tid&7), base row tid>>3 (0..31)
    const int crow = tid >> 3;
    const int cchk = tid & 7;

    float acc[4][8][4] = {};          // [mi][n8][reg]

    const int KITER = K_DIM / BKH;    // 64

    // Prologue: fill stages 0..STAGES-2
#pragma unroll
    for (int s = 0; s < STAGES - 1; s++) {
        const __half* ga = Ag + (size_t)s * BKH + cchk * 8;
        const __half* gb = Bg + (size_t)s * BKH + cchk * 8;
        uint32_t as = sbase + s * STAGE_BYTES;
        uint32_t bs = as + A_STAGE;
#pragma unroll
        for (int i = 0; i < 4; i++) {
            int r = crow + i * 32;
            cp16(as + sw_off(r, cchk), ga + (size_t)r * K_DIM);
        }
#pragma unroll
        for (int i = 0; i < 8; i++) {
            int r = crow + i * 32;
            cp16(bs + sw_off(r, cchk), gb + (size_t)r * K_DIM);
        }
        CP_COMMIT();
    }

    for (int it = 0; it < KITER; it++) {
        CP_WAIT(STAGES - 2);
        __syncthreads();              // single barrier per chunk: also protects
                                      // the stage about to be overwritten below

        // Issue loads for stage it+STAGES-1 (overlaps with compute below)
        int nk = it + STAGES - 1;
        if (nk < KITER) {
            int s = nk % STAGES;
            const __half* ga = Ag + (size_t)nk * BKH + cchk * 8;
            const __half* gb = Bg + (size_t)nk * BKH + cchk * 8;
            uint32_t as = sbase + s * STAGE_BYTES;
            uint32_t bs = as + A_STAGE;
#pragma unroll
            for (int i = 0; i < 4; i++) {
                int r = crow + i * 32;
                cp16(as + sw_off(r, cchk), ga + (size_t)r * K_DIM);
            }
#pragma unroll
            for (int i = 0; i < 8; i++) {
                int r = crow + i * 32;
                cp16(bs + sw_off(r, cchk), gb + (size_t)r * K_DIM);
            }
            CP_COMMIT();
        } else {
            CP_COMMIT();              // keep group count aligned with CP_WAIT
        }

        // Compute on stage it%STAGES
        const uint32_t As = sbase + (it % STAGES) * STAGE_BYTES;
        const uint32_t Bs = As + A_STAGE;
#pragma unroll
        for (int ks = 0; ks < 4; ks++) {
            const int ch = ks * 2 + (lane >> 4);
            uint32_t a[4][4];
#pragma unroll
            for (int mi = 0; mi < 4; mi++) {
                int r = wm * 64 + mi * 16 + (lane & 15);
                ldsm_x4(a[mi][0], a[mi][1], a[mi][2], a[mi][3], As + sw_off(r, ch));
            }
            uint32_t b[4][4];
#pragma unroll
            for (int nj = 0; nj < 4; nj++) {
                int r = wn * 64 + nj * 16 + (lane & 15);
                ldsm_x4(b[nj][0], b[nj][1], b[nj][2], b[nj][3], Bs + sw_off(r, ch));
            }
#pragma unroll
            for (int mi = 0; mi < 4; mi++)
#pragma unroll
                for (int n8 = 0; n8 < 8; n8++) {
                    int nj = n8 >> 1, hi = n8 & 1;
                    mma_16816(acc[mi][n8], a[mi], b[nj][hi], b[nj][hi + 2]);
                }
        }
    }

    // Fused epilogue: scale_b + fp16 quantize, store fp32
#pragma unroll
    for (int mi = 0; mi < 4; mi++) {
#pragma unroll
        for (int n8 = 0; n8 < 8; n8++) {
            const float* c = acc[mi][n8];
            int row = bm + wm * 64 + mi * 16 + (lane >> 2);
            int col = bn + wn * 64 + n8 * 8 + (lane & 3) * 2;
            float2 s0 = *(const float2*)&scale_b[col];
            float2 v0;
            v0.x = __half2float(__float2half(c[0] * s0.x));
            v0.y = __half2float(__float2half(c[1] * s0.y));
            *(float2*)&out[(size_t)row * N_DIM + col] = v0;
            float2 v1;
            v1.x = __half2float(__float2half(c[2] * s0.x));
            v1.y = __half2float(__float2half(c[3] * s0.y));
            *(float2*)&out[(size_t)(row + 8) * N_DIM + col] = v1;
        }
    }
}

// ---------------------------------------------------------------------------
// Host
// ---------------------------------------------------------------------------
extern "C" void kernel_launch(void* const* d_in, const int* in_sizes, int n_in,
                              void* d_out, int out_size) {
    const float* input = nullptr; const float* weight = nullptr; const float* scale_b = nullptr;
    long long input_elems = 0;
    for (int i = 0; i < n_in; i++) {
        long long sz = in_sizes[i];
        if (sz == (long long)K_DIM * N_DIM && !weight)      weight = (const float*)d_in[i];
        else if (sz == N_DIM && !scale_b)                   scale_b = (const float*)d_in[i];
        else if (sz > (long long)K_DIM * N_DIM)             { input = (const float*)d_in[i]; input_elems = sz; }
    }
    float* out = (float*)d_out;   // harness output buffer is FLOAT32

    long long M_full   = input_elems / K_DIM;
    long long out_rows = (long long)out_size / N_DIM;
    int world = (int)(M_full / (out_rows > 0 ? out_rows : M_full));
    if (world < 1) world = 1;
    int M_out = (int)(M_full / world);

    {
        int shard4 = (M_out * K_DIM) / 4;
        int rblocks = (shard4 + 255) / 256;
        int tblocks = (N_DIM / 32) * (K_DIM / 32);
        prep_kernel<<<rblocks + tblocks, 256>>>(input, weight, shard4, world, rblocks);
    }
    {
        cudaFuncSetAttribute(gemm_mma_kernel, cudaFuncAttributeMaxDynamicSharedMemorySize,
                             GEMM_SMEM);
        dim3 grid(N_DIM / BN, M_out / BM);
        gemm_mma_kernel<<<grid, 256, GEMM_SMEM>>>(scale_b, out);
    }
}

// round 10
// speedup vs baseline: 6.5548x; 1.0248x over previous
#include <cuda_runtime.h>
#include <cuda_fp16.h>
#include <cuda_fp8.h>
#include <cstdint>

// Problem shapes (fixed by the dataset)
#define M_FULL  16384
#define N_DIM   4096
#define K_DIM   4096

// Scratch (allocation-free rule: __device__ globals)
__device__ __half g_A16[(size_t)(M_FULL / 2) * K_DIM];  // fp16 Asum [M][K]
__device__ __half g_B16[(size_t)K_DIM * N_DIM];          // fp16 B^T [N][K]

// ---------------------------------------------------------------------------
// fp8 helpers
// ---------------------------------------------------------------------------
__device__ __forceinline__ float fp8_round(float x) {
    __nv_fp8_storage_t s = __nv_cvt_float_to_fp8(x, __NV_SATFINITE, __NV_E4M3);
    __half_raw hr = __nv_cvt_fp8_to_halfraw(s, __NV_E4M3);
    return __half2float(__half(hr));
}
__device__ __forceinline__ __half fp8_to_half(float x) {
    __nv_fp8_storage_t s = __nv_cvt_float_to_fp8(x, __NV_SATFINITE, __NV_E4M3);
    __half_raw hr = __nv_cvt_fp8_to_halfraw(s, __NV_E4M3);  // e4m3 exact in fp16
    return __half(hr);
}

// ---------------------------------------------------------------------------
// Fused prep kernel:
//   part 1 (blocks [0, rblocks)): Asum = sum_w fp8round(A_w), fp32 acc -> fp16
//   part 2 (rest):               W [K][N] f32 -> g_B16 = B^T [N][K] fp16
// ---------------------------------------------------------------------------
__global__ __launch_bounds__(256)
void prep_kernel(const float* __restrict__ A, const float* __restrict__ W,
                 int shard4, int world, int rblocks) {
    if ((int)blockIdx.x < rblocks) {
        int idx = blockIdx.x * 256 + threadIdx.x;
        if (idx >= shard4) return;
        const float4* A4 = (const float4*)A;
        float4 s = make_float4(0.f, 0.f, 0.f, 0.f);
        for (int w = 0; w < world; w++) {
            float4 v = A4[(size_t)w * shard4 + idx];
            s.x += fp8_round(v.x);
            s.y += fp8_round(v.y);
            s.z += fp8_round(v.z);
            s.w += fp8_round(v.w);
        }
        ((__half2*)g_A16)[idx * 2 + 0] = __floats2half2_rn(s.x, s.y);
        ((__half2*)g_A16)[idx * 2 + 1] = __floats2half2_rn(s.z, s.w);
    } else {
        __shared__ float t[32][33];
        int q = blockIdx.x - rblocks;              // 0 .. 128*128-1
        int n0 = (q & 127) * 32;
        int k0 = (q >> 7) * 32;
        int tx = threadIdx.x & 31, ty = threadIdx.x >> 5;   // (32, 8)
#pragma unroll
        for (int i = 0; i < 4; i++)
            t[ty + 8 * i][tx] = W[(size_t)(k0 + ty + 8 * i) * N_DIM + n0 + tx];
        __syncthreads();
#pragma unroll
        for (int i = 0; i < 4; i++)
            g_B16[(size_t)(n0 + ty + 8 * i) * K_DIM + k0 + tx] = fp8_to_half(t[tx][ty + 8 * i]);
    }
}

// ---------------------------------------------------------------------------
// PTX helpers (sm_80-era instructions; valid on compute_103)
// ---------------------------------------------------------------------------
__device__ __forceinline__ uint32_t smem_u32(const void* p) {
    uint32_t a;
    asm("{ .reg .u64 t; cvta.to.shared.u64 t, %1; cvt.u32.u64 %0, t; }" : "=r"(a) : "l"(p));
    return a;
}
__device__ __forceinline__ void ldsm_x4(uint32_t& r0, uint32_t& r1, uint32_t& r2, uint32_t& r3,
                                        uint32_t addr) {
    asm volatile("ldmatrix.sync.aligned.m8n8.x4.shared.b16 {%0,%1,%2,%3}, [%4];"
                 : "=r"(r0), "=r"(r1), "=r"(r2), "=r"(r3) : "r"(addr));
}
__device__ __forceinline__ void mma_16816(float* c, const uint32_t* a, uint32_t b0, uint32_t b1) {
    asm volatile("mma.sync.aligned.m16n8k16.row.col.f32.f16.f16.f32 "
                 "{%0,%1,%2,%3}, {%4,%5,%6,%7}, {%8,%9}, {%0,%1,%2,%3};"
                 : "+f"(c[0]), "+f"(c[1]), "+f"(c[2]), "+f"(c[3])
                 : "r"(a[0]), "r"(a[1]), "r"(a[2]), "r"(a[3]), "r"(b0), "r"(b1));
}
__device__ __forceinline__ void cp16(uint32_t smem, const void* g) {
    asm volatile("cp.async.cg.shared.global [%0], [%1], 16;" :: "r"(smem), "l"(g) : "memory");
}
#define CP_COMMIT() asm volatile("cp.async.commit_group;" ::: "memory")
#define CP_WAIT(n)  asm volatile("cp.async.wait_group %0;" :: "n"(n) : "memory")

// ---------------------------------------------------------------------------
// GEMM: 128x128 CTA tile, 128 threads (4 warps, warp tile 64x64), BK=64,
//       3-stage cp.async, 2 CTAs/SM, fused scale_b + fp16-round epilogue.
// ---------------------------------------------------------------------------
#define BM 128
#define BN 128
#define BKH 64                        // halves per stage chunk (128 B rows)
#define STAGES 3
#define ROWB 128                      // bytes per smem row
#define A_STAGE (BM * ROWB)           // 16 KB
#define B_STAGE (BN * ROWB)           // 16 KB
#define STAGE_BYTES (A_STAGE + B_STAGE)
#define GEMM_SMEM (STAGES * STAGE_BYTES)   // 96 KB -> 2 CTAs/SM

__device__ __forceinline__ uint32_t sw_off(int row, int chunk) {
    return (uint32_t)(row * ROWB + ((chunk ^ (row & 7)) << 4));
}

__global__ __launch_bounds__(128, 2)
void gemm_mma_kernel(const float* __restrict__ scale_b, float* __restrict__ out) {
    extern __shared__ char sm[];
    const uint32_t sbase = smem_u32(sm);

    const int tid  = threadIdx.x;
    const int lane = tid & 31;
    const int warp = tid >> 5;        // 0..3
    const int wm   = warp & 1;        // 0..1 -> 64-row group
    const int wn   = warp >> 1;       // 0..1 -> 64-col group
    const int bm = blockIdx.y * BM;
    const int bn = blockIdx.x * BN;

    const __half* Ag = g_A16 + (size_t)bm * K_DIM;
    const __half* Bg = g_B16 + (size_t)bn * K_DIM;

    // cp.async mapping: thread owns chunk (tid&7), base row tid>>3 (0..15)
    const int crow = tid >> 3;
    const int cchk = tid & 7;

    float acc[4][8][4] = {};          // [mi][n8][reg]

    const int KITER = K_DIM / BKH;    // 64

    // Prologue: fill stages 0..STAGES-2
#pragma unroll
    for (int s = 0; s < STAGES - 1; s++) {
        const __half* ga = Ag + (size_t)s * BKH + cchk * 8;
        const __half* gb = Bg + (size_t)s * BKH + cchk * 8;
        uint32_t as = sbase + s * STAGE_BYTES;
        uint32_t bs = as + A_STAGE;
#pragma unroll
        for (int i = 0; i < 8; i++) {
            int r = crow + i * 16;
            cp16(as + sw_off(r, cchk), ga + (size_t)r * K_DIM);
            cp16(bs + sw_off(r, cchk), gb + (size_t)r * K_DIM);
        }
        CP_COMMIT();
    }

    for (int it = 0; it < KITER; it++) {
        CP_WAIT(STAGES - 2);
        __syncthreads();              // protects the stage about to be reused

        // Issue loads for stage it+STAGES-1 (overlaps with compute below)
        int nk = it + STAGES - 1;
        if (nk < KITER) {
            int s = nk % STAGES;
            const __half* ga = Ag + (size_t)nk * BKH + cchk * 8;
            const __half* gb = Bg + (size_t)nk * BKH + cchk * 8;
            uint32_t as = sbase + s * STAGE_BYTES;
            uint32_t bs = as + A_STAGE;
#pragma unroll
            for (int i = 0; i < 8; i++) {
                int r = crow + i * 16;
                cp16(as + sw_off(r, cchk), ga + (size_t)r * K_DIM);
                cp16(bs + sw_off(r, cchk), gb + (size_t)r * K_DIM);
            }
            CP_COMMIT();
        } else {
            CP_COMMIT();              // keep group count aligned with CP_WAIT
        }

        // Compute on stage it%STAGES
        const uint32_t As = sbase + (it % STAGES) * STAGE_BYTES;
        const uint32_t Bs = As + A_STAGE;
#pragma unroll
        for (int ks = 0; ks < 4; ks++) {
            const int ch = ks * 2 + (lane >> 4);
            uint32_t a[4][4];
#pragma unroll
            for (int mi = 0; mi < 4; mi++) {
                int r = wm * 64 + mi * 16 + (lane & 15);
                ldsm_x4(a[mi][0], a[mi][1], a[mi][2], a[mi][3], As + sw_off(r, ch));
            }
            uint32_t b[4][4];
#pragma unroll
            for (int nj = 0; nj < 4; nj++) {
                int r = wn * 64 + nj * 16 + (lane & 15);
                ldsm_x4(b[nj][0], b[nj][1], b[nj][2], b[nj][3], Bs + sw_off(r, ch));
            }
#pragma unroll
            for (int mi = 0; mi < 4; mi++)
#pragma unroll
                for (int n8 = 0; n8 < 8; n8++) {
                    int nj = n8 >> 1, hi = n8 & 1;
                    mma_16816(acc[mi][n8], a[mi], b[nj][hi], b[nj][hi + 2]);
                }
        }
    }

    // Fused epilogue: scale_b + fp16 quantize, store fp32
#pragma unroll
    for (int mi = 0; mi < 4; mi++) {
#pragma unroll
        for (int n8 = 0; n8 < 8; n8++) {
            const float* c = acc[mi][n8];
            int row = bm + wm * 64 + mi * 16 + (lane >> 2);
            int col = bn + wn * 64 + n8 * 8 + (lane & 3) * 2;
            float2 s0 = *(const float2*)&scale_b[col];
            float2 v0;
            v0.x = __half2float(__float2half(c[0] * s0.x));
            v0.y = __half2float(__float2half(c[1] * s0.y));
            *(float2*)&out[(size_t)row * N_DIM + col] = v0;
            float2 v1;
            v1.x = __half2float(__float2half(c[2] * s0.x));
            v1.y = __half2float(__float2half(c[3] * s0.y));
            *(float2*)&out[(size_t)(row + 8) * N_DIM + col] = v1;
        }
    }
}

// ---------------------------------------------------------------------------
// Host
// ---------------------------------------------------------------------------
extern "C" void kernel_launch(void* const* d_in, const int* in_sizes, int n_in,
                              void* d_out, int out_size) {
    const float* input = nullptr; const float* weight = nullptr; const float* scale_b = nullptr;
    long long input_elems = 0;
    for (int i = 0; i < n_in; i++) {
        long long sz = in_sizes[i];
        if (sz == (long long)K_DIM * N_DIM && !weight)      weight = (const float*)d_in[i];
        else if (sz == N_DIM && !scale_b)                   scale_b = (const float*)d_in[i];
        else if (sz > (long long)K_DIM * N_DIM)             { input = (const float*)d_in[i]; input_elems = sz; }
    }
    float* out = (float*)d_out;   // harness output buffer is FLOAT32

    long long M_full   = input_elems / K_DIM;
    long long out_rows = (long long)out_size / N_DIM;
    int world = (int)(M_full / (out_rows > 0 ? out_rows : M_full));
    if (world < 1) world = 1;
    int M_out = (int)(M_full / world);

    {
        int shard4 = (M_out * K_DIM) / 4;
        int rblocks = (shard4 + 255) / 256;
        int tblocks = (N_DIM / 32) * (K_DIM / 32);
        prep_kernel<<<rblocks + tblocks, 256>>>(input, weight, shard4, world, rblocks);
    }
    {
        cudaFuncSetAttribute(gemm_mma_kernel, cudaFuncAttributeMaxDynamicSharedMemorySize,
                             GEMM_SMEM);
        dim3 grid(N_DIM / BN, M_out / BM);
        gemm_mma_kernel<<<grid, 128, GEMM_SMEM>>>(scale_b, out);
    }
}